// round 1
// baseline (speedup 1.0000x reference)
#include <cuda_runtime.h>
#include <cuda_bf16.h>
#include <math.h>

// ---------------- problem constants ----------------
#define Bz   8
#define BS   512
#define Tz   1536          // 3*BS
#define Dz   768
#define Hz   12
#define HDz  64
#define Lz   12
#define Fz   3072          // 4*D
#define NMz  438
#define Mz   (Bz*Tz)       // 12288 rows

// ---------------- scratch (device globals; allocation-free) ----------------
__device__ float g_x [Mz*Dz];
__device__ float g_h [Mz*Dz];
__device__ float g_q [Mz*Dz];
__device__ float g_k [Mz*Dz];
__device__ float g_v [Mz*Dz];
__device__ float g_y [Mz*Dz];
__device__ float g_ff[Mz*Fz];

// ---------------- embedding ----------------
__global__ void __launch_bounds__(256) embed_kernel(
    const int* __restrict__ idx_up, const int* __restrict__ idx_down,
    const float* __restrict__ cond, const float* __restrict__ teu,
    const float* __restrict__ ted, const float* __restrict__ pos,
    const float* __restrict__ cw, const float* __restrict__ cb,
    float* __restrict__ x)
{
    int row = blockIdx.x;                 // B*T rows
    int b = row / Tz, i = row % Tz;
    int seg = i >> 9, p = i & 511;
    __shared__ float cs[NMz];
    float o[3];
    if (seg == 0) {
        for (int kk = threadIdx.x; kk < NMz; kk += 256)
            cs[kk] = cond[((size_t)(b*BS + p))*NMz + kk];
        __syncthreads();
        #pragma unroll
        for (int j = 0; j < 3; ++j) {
            int d = threadIdx.x + j*256;
            float acc = cb[d];
            for (int kk = 0; kk < NMz; ++kk)
                acc = fmaf(cs[kk], cw[kk*Dz + d], acc);
            o[j] = acc;
        }
    } else {
        int tok = (seg == 1) ? idx_up[b*BS + p] : idx_down[b*BS + p];
        const float* te = (seg == 1) ? teu : ted;
        #pragma unroll
        for (int j = 0; j < 3; ++j)
            o[j] = te[(size_t)tok*Dz + threadIdx.x + j*256];
    }
    #pragma unroll
    for (int j = 0; j < 3; ++j) {
        int d = threadIdx.x + j*256;
        // t == BS, so pos row for global position i is just pos_emb[i]
        x[(size_t)row*Dz + d] = o[j] + pos[(size_t)i*Dz + d];
    }
}

// ---------------- layernorm (one block per row) ----------------
__global__ void __launch_bounds__(256) ln_kernel(
    const float* __restrict__ x, const float* __restrict__ w,
    const float* __restrict__ bb, float* __restrict__ o)
{
    int row = blockIdx.x;
    const float* xr = x + (size_t)row * Dz;
    int t = threadIdx.x, lane = t & 31, wid = t >> 5;
    float a0 = xr[t], a1 = xr[t+256], a2 = xr[t+512];
    float s = a0 + a1 + a2;
    __shared__ float red[8];
    #pragma unroll
    for (int off = 16; off; off >>= 1) s += __shfl_xor_sync(~0u, s, off);
    if (!lane) red[wid] = s;
    __syncthreads();
    s = red[0]+red[1]+red[2]+red[3]+red[4]+red[5]+red[6]+red[7];
    float mean = s * (1.0f/768.0f);
    float d0 = a0-mean, d1 = a1-mean, d2 = a2-mean;
    float sq = d0*d0 + d1*d1 + d2*d2;
    __syncthreads();
    #pragma unroll
    for (int off = 16; off; off >>= 1) sq += __shfl_xor_sync(~0u, sq, off);
    if (!lane) red[wid] = sq;
    __syncthreads();
    sq = red[0]+red[1]+red[2]+red[3]+red[4]+red[5]+red[6]+red[7];
    float rstd = rsqrtf(sq * (1.0f/768.0f) + 1e-5f);
    float* orow = o + (size_t)row * Dz;
    orow[t]     = d0*rstd*w[t]     + bb[t];
    orow[t+256] = d1*rstd*w[t+256] + bb[t+256];
    orow[t+512] = d2*rstd*w[t+512] + bb[t+512];
}

// ---------------- SGEMM: C[M,N] = A[M,K] @ W[K,N] + bias (+gelu | +res) ----------------
// epi: 0 = bias only, 1 = bias + exact GELU, 2 = bias + residual add
#define BM 128
#define BN 128
#define BKc 8
__global__ void __launch_bounds__(256) sgemm_kernel(
    const float* __restrict__ A, const float* __restrict__ W,
    const float* __restrict__ bias, const float* __restrict__ res,
    float* __restrict__ C, int M, int N, int K, int epi)
{
    __shared__ float As[BKc][BM];
    __shared__ float Bs[BKc][BN];
    int row0 = blockIdx.y * BM, col0 = blockIdx.x * BN;
    int tid = threadIdx.x;
    int ty = tid >> 4, tx = tid & 15;
    float acc[8][8];
    #pragma unroll
    for (int i = 0; i < 8; ++i)
        #pragma unroll
        for (int j = 0; j < 8; ++j) acc[i][j] = 0.0f;

    int arow = tid >> 1, ac4 = (tid & 1) * 4;
    int brow = tid >> 5, bc4 = (tid & 31) * 4;
    const float* Aptr = A + (size_t)(row0 + arow) * K + ac4;
    const float* Wptr = W + (size_t)brow * N + col0 + bc4;

    for (int k0 = 0; k0 < K; k0 += BKc) {
        float4 av = *(const float4*)(Aptr + k0);
        As[ac4+0][arow] = av.x; As[ac4+1][arow] = av.y;
        As[ac4+2][arow] = av.z; As[ac4+3][arow] = av.w;
        *(float4*)&Bs[brow][bc4] = *(const float4*)(Wptr + (size_t)k0 * N);
        __syncthreads();
        #pragma unroll
        for (int kk = 0; kk < BKc; ++kk) {
            float ra[8], rb[8];
            #pragma unroll
            for (int i = 0; i < 8; ++i) ra[i] = As[kk][ty*8 + i];
            #pragma unroll
            for (int j = 0; j < 8; ++j) rb[j] = Bs[kk][tx*8 + j];
            #pragma unroll
            for (int i = 0; i < 8; ++i)
                #pragma unroll
                for (int j = 0; j < 8; ++j)
                    acc[i][j] = fmaf(ra[i], rb[j], acc[i][j]);
        }
        __syncthreads();
    }
    #pragma unroll
    for (int i = 0; i < 8; ++i) {
        int r = row0 + ty*8 + i;
        #pragma unroll
        for (int j = 0; j < 8; ++j) {
            int c = col0 + tx*8 + j;
            float val = acc[i][j] + bias[c];
            if (epi == 1)      val = 0.5f * val * (1.0f + erff(val * 0.70710678118654752f));
            else if (epi == 2) val += res[(size_t)r * N + c];
            C[(size_t)r * N + c] = val;
        }
    }
}

// ---------------- flash attention (fp32, online softmax) ----------------
// Layout: q/k/v/y are [B, T, H, HD] == the [M, D] gemm output reinterpreted.
// Mask: 3x3 tiled causal -> key j valid iff (j % 512) <= (i % 512).
// One warp per query row; 8 warps/block share (b, h) and 8 consecutive i.
__global__ void __launch_bounds__(256) attn_kernel(
    const float* __restrict__ q, const float* __restrict__ k,
    const float* __restrict__ v, float* __restrict__ y)
{
    int idx0 = blockIdx.x * 8;               // index in b*H*T + h*T + i space
    int b   = idx0 / (Hz * Tz);
    int rem = idx0 % (Hz * Tz);
    int h   = rem / Tz;
    int i0  = rem % Tz;                      // multiple of 8, same segment chunk
    int warp = threadIdx.x >> 5, lane = threadIdx.x & 31;
    int i  = i0 + warp;
    int qi = i & 511;
    int qmax = (i0 & 511) + 7;               // block-wide max segment-local index

    __shared__ float ks[32][65];
    __shared__ float vs[32][65];

    const float* qrow = q + ((size_t)(b*Tz + i)) * Dz + h * HDz;
    float q0 = qrow[lane], q1 = qrow[lane + 32];
    float m = -1e30f, lsum = 0.0f, acc0 = 0.0f, acc1 = 0.0f;
    const float scale = 0.125f;              // 1/sqrt(64)

    for (int s = 0; s < 3; ++s) {
        int jbase = s * 512;
        for (int jt = 0; jt <= qmax; jt += 32) {
            __syncthreads();
            {   // stage 32 keys + values (coalesced): 8 floats each per thread
                int r  = threadIdx.x >> 3;
                int c0 = (threadIdx.x & 7) * 8;
                int j  = jbase + jt + r;     // always < jbase+512 (in bounds)
                const float* kp = k + ((size_t)(b*Tz + j)) * Dz + h * HDz + c0;
                const float* vp = v + ((size_t)(b*Tz + j)) * Dz + h * HDz + c0;
                #pragma unroll
                for (int c = 0; c < 8; ++c) { ks[r][c0+c] = kp[c]; vs[r][c0+c] = vp[c]; }
            }
            __syncthreads();
            int nblk = qmax - jt + 1; if (nblk > 32) nblk = 32;
            for (int jj = 0; jj < nblk; ++jj) {
                if (jt + jj > qi) break;     // warp-local causal cutoff
                float partial = q0 * ks[jj][lane] + q1 * ks[jj][lane + 32];
                #pragma unroll
                for (int off = 16; off; off >>= 1)
                    partial += __shfl_xor_sync(~0u, partial, off);
                float sc   = partial * scale;
                float mnew = fmaxf(m, sc);
                float corr = __expf(m - mnew);
                float p    = __expf(sc - mnew);
                lsum = lsum * corr + p;
                acc0 = acc0 * corr + p * vs[jj][lane];
                acc1 = acc1 * corr + p * vs[jj][lane + 32];
                m = mnew;
            }
        }
    }
    float inv = 1.0f / lsum;
    float* yrow = y + ((size_t)(b*Tz + i)) * Dz + h * HDz;
    yrow[lane]      = acc0 * inv;
    yrow[lane + 32] = acc1 * inv;
}

// ---------------- launch ----------------
extern "C" void kernel_launch(void* const* d_in, const int* in_sizes, int n_in,
                              void* d_out, int out_size)
{
    const int*   idx_up   = (const int*)  d_in[0];
    const int*   idx_down = (const int*)  d_in[1];
    const float* cond     = (const float*)d_in[2];
    const float* teu      = (const float*)d_in[3];
    const float* ted      = (const float*)d_in[4];
    const float* pos      = (const float*)d_in[5];
    const float* cw       = (const float*)d_in[6];
    const float* cb       = (const float*)d_in[7];
    const float* ln1w     = (const float*)d_in[8];
    const float* ln1b     = (const float*)d_in[9];
    const float* ln2w     = (const float*)d_in[10];
    const float* ln2b     = (const float*)d_in[11];
    const float* Wq       = (const float*)d_in[12];
    const float* bq       = (const float*)d_in[13];
    const float* Wk       = (const float*)d_in[14];
    const float* bk       = (const float*)d_in[15];
    const float* Wv       = (const float*)d_in[16];
    const float* bv       = (const float*)d_in[17];
    const float* Wp       = (const float*)d_in[18];
    const float* bp       = (const float*)d_in[19];
    const float* W1       = (const float*)d_in[20];
    const float* b1       = (const float*)d_in[21];
    const float* W2       = (const float*)d_in[22];
    const float* b2       = (const float*)d_in[23];

    float *x, *h, *q, *k, *v, *y, *ff;
    cudaGetSymbolAddress((void**)&x,  g_x);
    cudaGetSymbolAddress((void**)&h,  g_h);
    cudaGetSymbolAddress((void**)&q,  g_q);
    cudaGetSymbolAddress((void**)&k,  g_k);
    cudaGetSymbolAddress((void**)&v,  g_v);
    cudaGetSymbolAddress((void**)&y,  g_y);
    cudaGetSymbolAddress((void**)&ff, g_ff);

    embed_kernel<<<Mz, 256>>>(idx_up, idx_down, cond, teu, ted, pos, cw, cb, x);

    dim3 gD(Dz/BN, Mz/BM);   // (6, 96)
    dim3 gF(Fz/BN, Mz/BM);   // (24, 96)

    for (int l = 0; l < Lz; ++l) {
        ln_kernel<<<Mz, 256>>>(x, ln1w + l*Dz, ln1b + l*Dz, h);
        sgemm_kernel<<<gD, 256>>>(h, Wq + (size_t)l*Dz*Dz, bq + l*Dz, nullptr, q, Mz, Dz, Dz, 0);
        sgemm_kernel<<<gD, 256>>>(h, Wk + (size_t)l*Dz*Dz, bk + l*Dz, nullptr, k, Mz, Dz, Dz, 0);
        sgemm_kernel<<<gD, 256>>>(h, Wv + (size_t)l*Dz*Dz, bv + l*Dz, nullptr, v, Mz, Dz, Dz, 0);
        attn_kernel<<<Bz*Hz*Tz/8, 256>>>(q, k, v, y);
        sgemm_kernel<<<gD, 256>>>(y, Wp + (size_t)l*Dz*Dz, bp + l*Dz, x, x, Mz, Dz, Dz, 2);
        ln_kernel<<<Mz, 256>>>(x, ln2w + l*Dz, ln2b + l*Dz, h);
        sgemm_kernel<<<gF, 256>>>(h, W1 + (size_t)l*Dz*Fz, b1 + l*Fz, nullptr, ff, Mz, Fz, Dz, 1);
        sgemm_kernel<<<gD, 256>>>(ff, W2 + (size_t)l*Fz*Dz, b2 + l*Dz, x, x, Mz, Dz, Fz, 2);
    }

    cudaMemcpyAsync(d_out, x, (size_t)out_size * sizeof(float),
                    cudaMemcpyDeviceToDevice, 0);
}

// round 4
// speedup vs baseline: 1.7874x; 1.7874x over previous
#include <cuda_runtime.h>
#include <cuda_bf16.h>
#include <math.h>
#include <stdint.h>

// ---------------- problem constants ----------------
#define Bz   8
#define BS   512
#define Tz   1536          // 3*BS
#define Dz   768
#define Hz   12
#define HDz  64
#define Lz   12
#define Fz   3072          // 4*D
#define NMz  438
#define Mz   (Bz*Tz)       // 12288 rows

// ---------------- helpers ----------------
__device__ __forceinline__ uint32_t smem_u32(const void* p) {
    uint32_t a;
    asm("{ .reg .u64 t; cvta.to.shared.u64 t, %1; cvt.u32.u64 %0, t; }" : "=r"(a) : "l"(p));
    return a;
}
__device__ __forceinline__ void ldmx4(uint32_t* r, uint32_t addr) {
    asm volatile("ldmatrix.sync.aligned.m8n8.x4.shared.b16 {%0,%1,%2,%3}, [%4];"
        : "=r"(r[0]), "=r"(r[1]), "=r"(r[2]), "=r"(r[3]) : "r"(addr));
}
__device__ __forceinline__ void mma16816(float* d, const uint32_t* a,
                                         uint32_t b0, uint32_t b1) {
    asm volatile("mma.sync.aligned.m16n8k16.row.col.f32.bf16.bf16.f32 "
        "{%0,%1,%2,%3}, {%4,%5,%6,%7}, {%8,%9}, {%0,%1,%2,%3};"
        : "+f"(d[0]), "+f"(d[1]), "+f"(d[2]), "+f"(d[3])
        : "r"(a[0]), "r"(a[1]), "r"(a[2]), "r"(a[3]), "r"(b0), "r"(b1));
}
__device__ __forceinline__ void cp16(uint32_t saddr, const void* gaddr) {
    asm volatile("cp.async.cg.shared.global [%0], [%1], 16;"
        :: "r"(saddr), "l"(gaddr) : "memory");
}
#define CP_COMMIT() asm volatile("cp.async.commit_group;" ::: "memory")
#define CP_WAIT1()  asm volatile("cp.async.wait_group 1;"  ::: "memory")
#define CP_WAIT0()  asm volatile("cp.async.wait_group 0;"  ::: "memory")

__device__ __forceinline__ void splitbf(float v, __nv_bfloat16& h, __nv_bfloat16& l) {
    h = __float2bfloat16(v);
    l = __float2bfloat16(v - __bfloat162float(h));
}

// ---------------- scratch ----------------
__device__ float g_x [Mz*Dz];
__device__ float g_q [Mz*Dz];
__device__ float g_k [Mz*Dz];
__device__ float g_v [Mz*Dz];
__device__ __nv_bfloat16 g_hh[Mz*Dz];
__device__ __nv_bfloat16 g_hl[Mz*Dz];
__device__ __nv_bfloat16 g_yh[Mz*Dz];
__device__ __nv_bfloat16 g_yl[Mz*Dz];
__device__ __nv_bfloat16 g_fh[Mz*Fz];
__device__ __nv_bfloat16 g_fl[Mz*Fz];
// transposed split weights [L][N][K]
__device__ __nv_bfloat16 g_wqh[Lz*Dz*Dz]; __device__ __nv_bfloat16 g_wql[Lz*Dz*Dz];
__device__ __nv_bfloat16 g_wkh[Lz*Dz*Dz]; __device__ __nv_bfloat16 g_wkl[Lz*Dz*Dz];
__device__ __nv_bfloat16 g_wvh[Lz*Dz*Dz]; __device__ __nv_bfloat16 g_wvl[Lz*Dz*Dz];
__device__ __nv_bfloat16 g_wph[Lz*Dz*Dz]; __device__ __nv_bfloat16 g_wpl[Lz*Dz*Dz];
__device__ __nv_bfloat16 g_w1h[Lz*Dz*Fz]; __device__ __nv_bfloat16 g_w1l[Lz*Dz*Fz];
__device__ __nv_bfloat16 g_w2h[Lz*Dz*Fz]; __device__ __nv_bfloat16 g_w2l[Lz*Dz*Fz];

// ---------------- weight split + transpose: W[L][K][N] -> hi/lo[L][N][K] ----------------
__global__ void __launch_bounds__(256) wsplit_kernel(
    const float* __restrict__ W, __nv_bfloat16* __restrict__ hi,
    __nv_bfloat16* __restrict__ lo, int K, int N)
{
    __shared__ float t[32][33];
    int lyr = blockIdx.z;
    const float* Wl = W + (size_t)lyr * K * N;
    size_t obase = (size_t)lyr * K * N;
    int k0 = blockIdx.y * 32, n0 = blockIdx.x * 32;
    int tx = threadIdx.x & 31, ty = threadIdx.x >> 5;
    #pragma unroll
    for (int i = 0; i < 4; ++i)
        t[ty + i*8][tx] = Wl[(size_t)(k0 + ty + i*8) * N + n0 + tx];
    __syncthreads();
    #pragma unroll
    for (int i = 0; i < 4; ++i) {
        int n = ty + i*8;
        float v = t[tx][n];
        __nv_bfloat16 h, l; splitbf(v, h, l);
        size_t o = obase + (size_t)(n0 + n) * K + k0 + tx;
        hi[o] = h; lo[o] = l;
    }
}

// ---------------- embedding ----------------
__global__ void __launch_bounds__(256) embed_kernel(
    const int* __restrict__ idx_up, const int* __restrict__ idx_down,
    const float* __restrict__ cond, const float* __restrict__ teu,
    const float* __restrict__ ted, const float* __restrict__ pos,
    const float* __restrict__ cw, const float* __restrict__ cb,
    float* __restrict__ x)
{
    int row = blockIdx.x;
    int b = row / Tz, i = row % Tz;
    int seg = i >> 9, p = i & 511;
    __shared__ float cs[NMz];
    float o[3];
    if (seg == 0) {
        for (int kk = threadIdx.x; kk < NMz; kk += 256)
            cs[kk] = cond[((size_t)(b*BS + p))*NMz + kk];
        __syncthreads();
        #pragma unroll
        for (int j = 0; j < 3; ++j) {
            int d = threadIdx.x + j*256;
            float acc = cb[d];
            for (int kk = 0; kk < NMz; ++kk)
                acc = fmaf(cs[kk], cw[kk*Dz + d], acc);
            o[j] = acc;
        }
    } else {
        int tok = (seg == 1) ? idx_up[b*BS + p] : idx_down[b*BS + p];
        const float* te = (seg == 1) ? teu : ted;
        #pragma unroll
        for (int j = 0; j < 3; ++j)
            o[j] = te[(size_t)tok*Dz + threadIdx.x + j*256];
    }
    #pragma unroll
    for (int j = 0; j < 3; ++j) {
        int d = threadIdx.x + j*256;
        x[(size_t)row*Dz + d] = o[j] + pos[(size_t)i*Dz + d];
    }
}

// ---------------- layernorm -> bf16 split ----------------
__global__ void __launch_bounds__(256) ln_kernel(
    const float* __restrict__ x, const float* __restrict__ w,
    const float* __restrict__ bb, __nv_bfloat16* __restrict__ oh,
    __nv_bfloat16* __restrict__ ol)
{
    int row = blockIdx.x;
    const float* xr = x + (size_t)row * Dz;
    int t = threadIdx.x, lane = t & 31, wid = t >> 5;
    float a0 = xr[t], a1 = xr[t+256], a2 = xr[t+512];
    float s = a0 + a1 + a2;
    __shared__ float red[8];
    #pragma unroll
    for (int off = 16; off; off >>= 1) s += __shfl_xor_sync(~0u, s, off);
    if (!lane) red[wid] = s;
    __syncthreads();
    s = red[0]+red[1]+red[2]+red[3]+red[4]+red[5]+red[6]+red[7];
    float mean = s * (1.0f/768.0f);
    float d0 = a0-mean, d1 = a1-mean, d2 = a2-mean;
    float sq = d0*d0 + d1*d1 + d2*d2;
    __syncthreads();
    #pragma unroll
    for (int off = 16; off; off >>= 1) sq += __shfl_xor_sync(~0u, sq, off);
    if (!lane) red[wid] = sq;
    __syncthreads();
    sq = red[0]+red[1]+red[2]+red[3]+red[4]+red[5]+red[6]+red[7];
    float rstd = rsqrtf(sq * (1.0f/768.0f) + 1e-5f);
    size_t ro = (size_t)row * Dz;
    float o0 = d0*rstd*w[t]     + bb[t];
    float o1 = d1*rstd*w[t+256] + bb[t+256];
    float o2 = d2*rstd*w[t+512] + bb[t+512];
    __nv_bfloat16 h, l;
    splitbf(o0, h, l); oh[ro+t]     = h; ol[ro+t]     = l;
    splitbf(o1, h, l); oh[ro+t+256] = h; ol[ro+t+256] = l;
    splitbf(o2, h, l); oh[ro+t+512] = h; ol[ro+t+512] = l;
}

// ---------------- bf16x3 tensor-core GEMM (mma.sync m16n8k16) ----------------
// C[128,128] per CTA = Ah*Bh^T + Ah*Bl^T + Al*Bh^T, fp32 accum.
// A: [M,K] bf16 K-major hi/lo. B: [N,K] bf16 K-major hi/lo (= W^T split).
// epi: 0 -> Cf = D+bias ; 1 -> gelu(D+bias) split -> Ch/Cl ; 2 -> Cf = D+bias+res
#define GKC 32
#define TILE_B 8192              // 128 rows * 64 bytes
#define STAGE_B (4*TILE_B)       // Ah, Al, Bh, Bl
#define GSMEM (2*STAGE_B)        // 64 KB
// smem chunk swizzle: row r (0..127), 16B-chunk c (0..3)
#define SWC(r, c) (((r) << 6) + ((((c) ^ (((r) & 7) >> 1))) << 4))

__global__ void __launch_bounds__(256, 1) gemm_kernel(
    const __nv_bfloat16* __restrict__ Ah, const __nv_bfloat16* __restrict__ Al,
    const __nv_bfloat16* __restrict__ Bh, const __nv_bfloat16* __restrict__ Bl,
    const float* __restrict__ bias, const float* __restrict__ res,
    float* __restrict__ Cf, __nv_bfloat16* __restrict__ Ch,
    __nv_bfloat16* __restrict__ Cl, int K, int N, int epi)
{
    extern __shared__ char smem[];
    uint32_t sb = smem_u32(smem);
    int tid = threadIdx.x, lane = tid & 31, wid = tid >> 5;
    int wm = wid & 1, wn = wid >> 1;            // warp grid 2(M) x 4(N)
    int row0 = blockIdx.y * 128, col0 = blockIdx.x * 128;

    float acc[4][4][4];
    #pragma unroll
    for (int a = 0; a < 4; ++a)
        #pragma unroll
        for (int b = 0; b < 4; ++b)
            #pragma unroll
            for (int c = 0; c < 4; ++c) acc[a][b][c] = 0.0f;

    // per-thread load slots: rows lr0 and lr0+64, 16B chunk lc0
    int lr0 = tid >> 2, lc0 = (tid & 3);

    const __nv_bfloat16* srcs[4] = {Ah, Al, Bh, Bl};
    int rbases[4] = {row0, row0, col0, col0};

    int T = K / GKC;
    // prologue: stage 0
    {
        #pragma unroll
        for (int t = 0; t < 4; ++t) {
            uint32_t tb = sb + t * TILE_B;
            const __nv_bfloat16* base = srcs[t] + (size_t)(rbases[t] + lr0) * K + lc0 * 8;
            cp16(tb + SWC(lr0,      lc0), base);
            cp16(tb + SWC(lr0 + 64, lc0), base + (size_t)64 * K);
        }
        CP_COMMIT();
    }

    int grp = lane >> 3, lrow = lane & 7;

    for (int kt = 0; kt < T; ++kt) {
        int buf = kt & 1;
        if (kt + 1 < T) {
            int kc0 = (kt + 1) * GKC;
            uint32_t stg = sb + ((kt + 1) & 1) * STAGE_B;
            #pragma unroll
            for (int t = 0; t < 4; ++t) {
                uint32_t tb = stg + t * TILE_B;
                const __nv_bfloat16* base = srcs[t] + (size_t)(rbases[t] + lr0) * K + kc0 + lc0 * 8;
                cp16(tb + SWC(lr0,      lc0), base);
                cp16(tb + SWC(lr0 + 64, lc0), base + (size_t)64 * K);
            }
            CP_COMMIT();
            CP_WAIT1();
        } else {
            CP_WAIT0();
        }
        __syncthreads();

        uint32_t As = sb + buf * STAGE_B;
        uint32_t Als = As + TILE_B, Bhs = As + 2*TILE_B, Bls = As + 3*TILE_B;

        #pragma unroll
        for (int ks = 0; ks < 2; ++ks) {
            // B fragments: 2 ldmatrix.x4 per hi/lo cover 32 n
            uint32_t bh[2][4], bl[2][4];
            #pragma unroll
            for (int bi = 0; bi < 2; ++bi) {
                int n = wn*32 + bi*16 + (grp >> 1)*8 + lrow;
                int c = ks*2 + (grp & 1);
                uint32_t off = SWC(n, c);
                ldmx4(bh[bi], Bhs + off);
                ldmx4(bl[bi], Bls + off);
            }
            #pragma unroll
            for (int mi = 0; mi < 4; ++mi) {
                int r = wm*64 + mi*16 + (grp & 1)*8 + lrow;
                int c = ks*2 + (grp >> 1);
                uint32_t off = SWC(r, c);
                uint32_t af[4], alf[4];
                ldmx4(af,  As  + off);
                ldmx4(alf, Als + off);
                #pragma unroll
                for (int nj = 0; nj < 4; ++nj) {
                    uint32_t b0h = bh[nj>>1][(nj&1)*2], b1h = bh[nj>>1][(nj&1)*2+1];
                    uint32_t b0l = bl[nj>>1][(nj&1)*2], b1l = bl[nj>>1][(nj&1)*2+1];
                    mma16816(acc[mi][nj], af,  b0h, b1h);
                    mma16816(acc[mi][nj], af,  b0l, b1l);
                    mma16816(acc[mi][nj], alf, b0h, b1h);
                }
            }
        }
        __syncthreads();
    }

    // epilogue: register -> gmem, fused bias (+gelu split | +res)
    #pragma unroll
    for (int mi = 0; mi < 4; ++mi) {
        #pragma unroll
        for (int nj = 0; nj < 4; ++nj) {
            int gr = row0 + wm*64 + mi*16 + (lane >> 2);
            int gc = col0 + wn*32 + nj*8 + (lane & 3)*2;
            float bz0 = bias[gc], bz1 = bias[gc + 1];
            #pragma unroll
            for (int half = 0; half < 2; ++half) {
                int r = gr + half*8;
                float v0 = acc[mi][nj][half*2]     + bz0;
                float v1 = acc[mi][nj][half*2 + 1] + bz1;
                size_t off = (size_t)r * N + gc;
                if (epi == 0) {
                    *(float2*)(Cf + off) = make_float2(v0, v1);
                } else if (epi == 2) {
                    float2 rv = *(const float2*)(res + off);
                    *(float2*)(Cf + off) = make_float2(v0 + rv.x, v1 + rv.y);
                } else {
                    float g0 = 0.5f*v0*(1.0f + erff(v0*0.70710678118654752f));
                    float g1 = 0.5f*v1*(1.0f + erff(v1*0.70710678118654752f));
                    __nv_bfloat16 h0,l0,h1,l1;
                    splitbf(g0,h0,l0); splitbf(g1,h1,l1);
                    *(__nv_bfloat162*)(Ch + off) = __halves2bfloat162(h0, h1);
                    *(__nv_bfloat162*)(Cl + off) = __halves2bfloat162(l0, l1);
                }
            }
        }
    }
}

// ---------------- flash attention: lane-parallel keys ----------------
// one warp per query; lane j handles key jt+j within a 32-key tile.
// K/V staged transposed: kst[d][j], vst[d][j] -> conflict-free LDS.
__global__ void __launch_bounds__(256) attn_kernel(
    const float* __restrict__ q, const float* __restrict__ k,
    const float* __restrict__ v, __nv_bfloat16* __restrict__ yh,
    __nv_bfloat16* __restrict__ yl)
{
    int idx0 = blockIdx.x * 8;
    int b   = idx0 / (Hz * Tz);
    int rem = idx0 % (Hz * Tz);
    int h   = rem / Tz;
    int i0  = rem % Tz;
    int warp = threadIdx.x >> 5, lane = threadIdx.x & 31;
    int i  = i0 + warp;
    int qi = i & 511;
    int qmax = (i0 & 511) + 7;

    __shared__ float kst[64][33];
    __shared__ float vst[64][33];
    __shared__ float qs[8][64];

    const float* qrow = q + ((size_t)(b*Tz + i)) * Dz + h * HDz;
    qs[warp][lane]      = qrow[lane];
    qs[warp][lane + 32] = qrow[lane + 32];

    float m = -1e30f, lsum = 0.0f, a0 = 0.0f, a1 = 0.0f;

    for (int s = 0; s < 3; ++s) {
        int jbase = s * 512;
        for (int jt = 0; jt <= qmax; jt += 32) {
            __syncthreads();
            {   // stage 32 keys+values transposed
                int r  = threadIdx.x >> 3;        // key 0..31
                int c0 = (threadIdx.x & 7) * 8;   // dim chunk
                const float* kp = k + ((size_t)(b*Tz + jbase + jt + r))*Dz + h*HDz + c0;
                const float* vp = v + ((size_t)(b*Tz + jbase + jt + r))*Dz + h*HDz + c0;
                #pragma unroll
                for (int c = 0; c < 8; ++c) {
                    kst[c0 + c][r] = kp[c];
                    vst[c0 + c][r] = vp[c];
                }
            }
            __syncthreads();
            if (jt <= qi) {
                float s0 = 0.f, s1 = 0.f, s2 = 0.f, s3 = 0.f;
                #pragma unroll 16
                for (int d = 0; d < 64; d += 4) {
                    s0 = fmaf(qs[warp][d+0], kst[d+0][lane], s0);
                    s1 = fmaf(qs[warp][d+1], kst[d+1][lane], s1);
                    s2 = fmaf(qs[warp][d+2], kst[d+2][lane], s2);
                    s3 = fmaf(qs[warp][d+3], kst[d+3][lane], s3);
                }
                float sc = (s0 + s1) + (s2 + s3);
                int nval = qi - jt + 1; if (nval > 32) nval = 32;
                sc = (lane < nval) ? sc * 0.125f : -1e30f;
                float tm = sc;
                #pragma unroll
                for (int off = 16; off; off >>= 1)
                    tm = fmaxf(tm, __shfl_xor_sync(~0u, tm, off));
                float mn   = fmaxf(m, tm);
                float corr = __expf(m - mn);
                float p    = __expf(sc - mn);
                float sp   = p;
                #pragma unroll
                for (int off = 16; off; off >>= 1)
                    sp += __shfl_xor_sync(~0u, sp, off);
                lsum = lsum * corr + sp;
                a0 *= corr; a1 *= corr;
                for (int j = 0; j < nval; ++j) {
                    float pj = __shfl_sync(~0u, p, j);
                    a0 = fmaf(pj, vst[lane][j],      a0);
                    a1 = fmaf(pj, vst[lane + 32][j], a1);
                }
                m = mn;
            }
        }
    }
    float inv = 1.0f / lsum;
    float o0 = a0 * inv, o1 = a1 * inv;
    size_t yo = ((size_t)(b*Tz + i)) * Dz + h * HDz;
    __nv_bfloat16 hh, ll;
    splitbf(o0, hh, ll); yh[yo + lane]      = hh; yl[yo + lane]      = ll;
    splitbf(o1, hh, ll); yh[yo + lane + 32] = hh; yl[yo + lane + 32] = ll;
}

// ---------------- launch ----------------
extern "C" void kernel_launch(void* const* d_in, const int* in_sizes, int n_in,
                              void* d_out, int out_size)
{
    const int*   idx_up   = (const int*)  d_in[0];
    const int*   idx_down = (const int*)  d_in[1];
    const float* cond     = (const float*)d_in[2];
    const float* teu      = (const float*)d_in[3];
    const float* ted      = (const float*)d_in[4];
    const float* pos      = (const float*)d_in[5];
    const float* cw       = (const float*)d_in[6];
    const float* cb       = (const float*)d_in[7];
    const float* ln1w     = (const float*)d_in[8];
    const float* ln1b     = (const float*)d_in[9];
    const float* ln2w     = (const float*)d_in[10];
    const float* ln2b     = (const float*)d_in[11];
    const float* Wq       = (const float*)d_in[12];
    const float* bq       = (const float*)d_in[13];
    const float* Wk       = (const float*)d_in[14];
    const float* bk       = (const float*)d_in[15];
    const float* Wv       = (const float*)d_in[16];
    const float* bv       = (const float*)d_in[17];
    const float* Wp       = (const float*)d_in[18];
    const float* bp       = (const float*)d_in[19];
    const float* W1       = (const float*)d_in[20];
    const float* b1       = (const float*)d_in[21];
    const float* W2       = (const float*)d_in[22];
    const float* b2       = (const float*)d_in[23];

    float *x, *q, *k, *v;
    __nv_bfloat16 *hh, *hl, *yh, *yl, *fh, *fl;
    __nv_bfloat16 *wqh, *wql, *wkh, *wkl, *wvh, *wvl, *wph, *wpl, *w1h, *w1l, *w2h, *w2l;
    cudaGetSymbolAddress((void**)&x,  g_x);
    cudaGetSymbolAddress((void**)&q,  g_q);
    cudaGetSymbolAddress((void**)&k,  g_k);
    cudaGetSymbolAddress((void**)&v,  g_v);
    cudaGetSymbolAddress((void**)&hh, g_hh); cudaGetSymbolAddress((void**)&hl, g_hl);
    cudaGetSymbolAddress((void**)&yh, g_yh); cudaGetSymbolAddress((void**)&yl, g_yl);
    cudaGetSymbolAddress((void**)&fh, g_fh); cudaGetSymbolAddress((void**)&fl, g_fl);
    cudaGetSymbolAddress((void**)&wqh, g_wqh); cudaGetSymbolAddress((void**)&wql, g_wql);
    cudaGetSymbolAddress((void**)&wkh, g_wkh); cudaGetSymbolAddress((void**)&wkl, g_wkl);
    cudaGetSymbolAddress((void**)&wvh, g_wvh); cudaGetSymbolAddress((void**)&wvl, g_wvl);
    cudaGetSymbolAddress((void**)&wph, g_wph); cudaGetSymbolAddress((void**)&wpl, g_wpl);
    cudaGetSymbolAddress((void**)&w1h, g_w1h); cudaGetSymbolAddress((void**)&w1l, g_w1l);
    cudaGetSymbolAddress((void**)&w2h, g_w2h); cudaGetSymbolAddress((void**)&w2l, g_w2l);

    cudaFuncSetAttribute(gemm_kernel, cudaFuncAttributeMaxDynamicSharedMemorySize, GSMEM);

    // weight prep: split + transpose to [N][K]
    wsplit_kernel<<<dim3(24, 24, Lz), 256>>>(Wq, wqh, wql, Dz, Dz);
    wsplit_kernel<<<dim3(24, 24, Lz), 256>>>(Wk, wkh, wkl, Dz, Dz);
    wsplit_kernel<<<dim3(24, 24, Lz), 256>>>(Wv, wvh, wvl, Dz, Dz);
    wsplit_kernel<<<dim3(24, 24, Lz), 256>>>(Wp, wph, wpl, Dz, Dz);
    wsplit_kernel<<<dim3(96, 24, Lz), 256>>>(W1, w1h, w1l, Dz, Fz);
    wsplit_kernel<<<dim3(24, 96, Lz), 256>>>(W2, w2h, w2l, Fz, Dz);

    embed_kernel<<<Mz, 256>>>(idx_up, idx_down, cond, teu, ted, pos, cw, cb, x);

    dim3 gD(Dz/128, Mz/128);   // (6, 96)
    dim3 gF(Fz/128, Mz/128);   // (24, 96)
    size_t DD = (size_t)Dz * Dz, DF = (size_t)Dz * Fz;

    for (int l = 0; l < Lz; ++l) {
        ln_kernel<<<Mz, 256>>>(x, ln1w + l*Dz, ln1b + l*Dz, hh, hl);
        gemm_kernel<<<gD, 256, GSMEM>>>(hh, hl, wqh + l*DD, wql + l*DD,
            bq + l*Dz, nullptr, q, nullptr, nullptr, Dz, Dz, 0);
        gemm_kernel<<<gD, 256, GSMEM>>>(hh, hl, wkh + l*DD, wkl + l*DD,
            bk + l*Dz, nullptr, k, nullptr, nullptr, Dz, Dz, 0);
        gemm_kernel<<<gD, 256, GSMEM>>>(hh, hl, wvh + l*DD, wvl + l*DD,
            bv + l*Dz, nullptr, v, nullptr, nullptr, Dz, Dz, 0);
        attn_kernel<<<Bz*Hz*Tz/8, 256>>>(q, k, v, yh, yl);
        gemm_kernel<<<gD, 256, GSMEM>>>(yh, yl, wph + l*DD, wpl + l*DD,
            bp + l*Dz, x, x, nullptr, nullptr, Dz, Dz, 2);
        ln_kernel<<<Mz, 256>>>(x, ln2w + l*Dz, ln2b + l*Dz, hh, hl);
        gemm_kernel<<<gF, 256, GSMEM>>>(hh, hl, w1h + l*DF, w1l + l*DF,
            b1 + l*Fz, nullptr, nullptr, fh, fl, Dz, Fz, 1);
        gemm_kernel<<<gD, 256, GSMEM>>>(fh, fl, w2h + l*DF, w2l + l*DF,
            b2 + l*Dz, x, x, nullptr, nullptr, Fz, Dz, 2);
    }

    cudaMemcpyAsync(d_out, x, (size_t)out_size * sizeof(float),
                    cudaMemcpyDeviceToDevice, 0);
}